// round 13
// baseline (speedup 1.0000x reference)
#include <cuda_runtime.h>
#include <cstdint>

// ---------------- problem constants ----------------
#define Nn 8
#define Cc 16
#define Ll 32
#define Dd 24
#define HW24 576
#define Ff 32
#define OL 30
#define OL2 15
#define OD 22
#define OE 22

// ---------------- scratch (fragment-baked layouts) ----------------
// g_xt: [n][l][d][s=576][tig=4] float4; slot tig = channels (tig, tig+4, tig+8, tig+12)
__device__ float g_xt[(size_t)Nn * Ll * Dd * HW24 * Cc + 4096];
// g_w2: [pt=81][nt=4][n=8][tig=4] float4; pt = lk*27 + dk*9 + hk*3 + wk; f = nt*8+n
__device__ float g_w2[9 * 9 * 4 * 8 * 16 + 512];

__device__ __forceinline__ uint32_t tf32_rna(float x) {
    uint32_t r;
    asm("cvt.rna.tf32.f32 %0, %1;" : "=r"(r) : "f"(x));
    return r;
}
__device__ __forceinline__ uint4 ldg128(const void* p) {
    return __ldg(reinterpret_cast<const uint4*>(p));
}
__device__ __forceinline__ void pf_l1(const void* p) {
    asm volatile("prefetch.global.L1 [%0];" :: "l"(p));
}
__device__ __forceinline__ void mma_tf32(float* d,
    uint32_t a0, uint32_t a1, uint32_t a2, uint32_t a3,
    uint32_t b0, uint32_t b1)
{
    asm volatile(
        "mma.sync.aligned.m16n8k8.row.col.f32.tf32.tf32.f32 "
        "{%0,%1,%2,%3}, {%4,%5,%6,%7}, {%8,%9}, {%0,%1,%2,%3};"
        : "+f"(d[0]), "+f"(d[1]), "+f"(d[2]), "+f"(d[3])
        : "r"(a0), "r"(a1), "r"(a2), "r"(a3), "r"(b0), "r"(b1));
}

// ---------------- prep ----------------
__global__ __launch_bounds__(256)
void prep_all(const float* __restrict__ x, const float* __restrict__ W) {
    int bid = blockIdx.x;
    if (bid < Nn * Ll * Dd) {
        __shared__ float sx[Cc][HW24 + 1];
        int D = bid % Dd;
        int L = (bid / Dd) % Ll;
        int n = bid / (Dd * Ll);
        for (int i4 = threadIdx.x; i4 < Cc * 144; i4 += 256) {
            int c = i4 / 144, r4 = i4 - c * 144;
            const float4 v = *reinterpret_cast<const float4*>(
                x + ((((size_t)(n * Cc + c) * Ll + L) * Dd + D) * HW24 + r4 * 4));
            sx[c][r4 * 4 + 0] = v.x; sx[c][r4 * 4 + 1] = v.y;
            sx[c][r4 * 4 + 2] = v.z; sx[c][r4 * 4 + 3] = v.w;
        }
        __syncthreads();
        float4* dst = reinterpret_cast<float4*>(g_xt + (size_t)bid * (HW24 * Cc));
        for (int i4 = threadIdx.x; i4 < HW24 * 4; i4 += 256) {
            int s = i4 >> 2, tig = i4 & 3;
            uint4 v;
            v.x = tf32_rna(sx[tig][s]);
            v.y = tf32_rna(sx[tig + 4][s]);
            v.z = tf32_rna(sx[tig + 8][s]);
            v.w = tf32_rna(sx[tig + 12][s]);
            dst[i4] = *reinterpret_cast<float4*>(&v);
        }
    } else {
        for (int i = threadIdx.x; i < 9 * 9 * 4 * 8 * 4; i += 256) {
            int tig = i & 3;
            int nrow = (i >> 2) & 7;
            int nt = (i >> 5) & 3;
            int pt = i >> 7;
            int f = nt * 8 + nrow;
            uint4 v;
            v.x = tf32_rna(W[((size_t)f * Cc + tig) * 81 + pt]);
            v.y = tf32_rna(W[((size_t)f * Cc + tig + 4) * 81 + pt]);
            v.z = tf32_rna(W[((size_t)f * Cc + tig + 8) * 81 + pt]);
            v.w = tf32_rna(W[((size_t)f * Cc + tig + 12) * 81 + pt]);
            reinterpret_cast<uint4*>(g_w2)[i] = v;
        }
    }
}

// ---------------- main kernel: 11 warps x m48, dual-l outputs, A-slab reuse ----------------
#define STAGE_F (16 * 33)
#define NW 11
#define NT (NW * 32)

// one output's 9-tap block: A loaded here, B from wt (tap stride 2048)
__device__ __forceinline__ void taps_one(float (&acc)[3][4][4],
                                         const char* xp, const char* wt) {
#pragma unroll
    for (int t = 0; t < 9; ++t) {
        const int off = (t / 3) * 24 + (t % 3);
        uint4 a0[3], a1[3];
#pragma unroll
        for (int mt = 0; mt < 3; mt++) {
            a0[mt] = ldg128(xp + (mt * 16 + off) * 64);
            a1[mt] = ldg128(xp + (mt * 16 + 8 + off) * 64);
        }
        uint4 b[4];
#pragma unroll
        for (int nt = 0; nt < 4; nt++) b[nt] = ldg128(wt + t * 2048 + nt * 512);
#pragma unroll
        for (int mt = 0; mt < 3; mt++)
#pragma unroll
            for (int nt = 0; nt < 4; nt++) {
                mma_tf32(acc[mt][nt], a0[mt].x, a1[mt].x, a0[mt].y, a1[mt].y,
                         b[nt].x, b[nt].y);
                mma_tf32(acc[mt][nt], a0[mt].z, a1[mt].z, a0[mt].w, a1[mt].w,
                         b[nt].z, b[nt].w);
            }
    }
}

// shared-A dual block: same A fragments feed acc0 (B=wtA) and acc1 (B=wtB)
__device__ __forceinline__ void taps_two(float (&ac0)[3][4][4], float (&ac1)[3][4][4],
                                         const char* xp, const char* wtA, const char* wtB) {
#pragma unroll
    for (int t = 0; t < 9; ++t) {
        const int off = (t / 3) * 24 + (t % 3);
        uint4 a0[3], a1[3];
#pragma unroll
        for (int mt = 0; mt < 3; mt++) {
            a0[mt] = ldg128(xp + (mt * 16 + off) * 64);
            a1[mt] = ldg128(xp + (mt * 16 + 8 + off) * 64);
        }
        {
            uint4 b[4];
#pragma unroll
            for (int nt = 0; nt < 4; nt++) b[nt] = ldg128(wtA + t * 2048 + nt * 512);
#pragma unroll
            for (int mt = 0; mt < 3; mt++)
#pragma unroll
                for (int nt = 0; nt < 4; nt++) {
                    mma_tf32(ac0[mt][nt], a0[mt].x, a1[mt].x, a0[mt].y, a1[mt].y,
                             b[nt].x, b[nt].y);
                    mma_tf32(ac0[mt][nt], a0[mt].z, a1[mt].z, a0[mt].w, a1[mt].w,
                             b[nt].z, b[nt].w);
                }
        }
        {
            uint4 b[4];
#pragma unroll
            for (int nt = 0; nt < 4; nt++) b[nt] = ldg128(wtB + t * 2048 + nt * 512);
#pragma unroll
            for (int mt = 0; mt < 3; mt++)
#pragma unroll
                for (int nt = 0; nt < 4; nt++) {
                    mma_tf32(ac1[mt][nt], a0[mt].x, a1[mt].x, a0[mt].y, a1[mt].y,
                             b[nt].x, b[nt].y);
                    mma_tf32(ac1[mt][nt], a0[mt].z, a1[mt].z, a0[mt].w, a1[mt].w,
                             b[nt].z, b[nt].w);
                }
        }
    }
}

__global__ __launch_bounds__(NT, 1)
void conv4d_mma(const float* __restrict__ bias, float* __restrict__ out) {
    __shared__ float stg[NW * STAGE_F];
    __shared__ float sbias[Ff];

    const int tid  = threadIdx.x;
    const int wid  = tid >> 5;          // 0..10
    const int lane = tid & 31;
    const int g    = lane >> 2;
    const int tig  = lane & 3;

    int bid = blockIdx.x;
    const int d  = bid % OD;
    const int li = (bid / OD) % OL2;
    const int n  = bid / (OD * OL2);
    const int l0 = 2 * li;

    if (tid < Ff) sbias[tid] = 3.0f * bias[tid];

    float acc0[3][4][4], acc1[3][4][4];
#pragma unroll
    for (int mt = 0; mt < 3; mt++)
#pragma unroll
        for (int nt = 0; nt < 4; nt++)
#pragma unroll
            for (int k = 0; k < 4; k++) { acc0[mt][nt][k] = 0.f; acc1[mt][nt][k] = 0.f; }

    // slab (l0+j, d+dk) base; L stride = Dd*36864 bytes, D stride = 36864 bytes
    const char* xblk = reinterpret_cast<const char*>(
        g_xt + ((size_t)((n * Ll + l0) * Dd) + d) * (HW24 * Cc));
    const char* xsl = xblk + (size_t)(wid * 48 + g) * 64 + tig * 16;
    const char* wb  = reinterpret_cast<const char*>(g_w2) + g * 64 + tig * 16;

#pragma unroll 1
    for (int j = 0; j < 4; ++j) {
#pragma unroll 1
        for (int dk = 0; dk < 3; ++dk) {
            // prefetch next plane's A lines
            {
                int nj = j, ndk = dk + 1;
                if (ndk == 3) { ndk = 0; nj = j + 1; }
                if (nj < 4 && tid < 288)
                    pf_l1(xblk + (size_t)(nj * Dd + ndk) * 36864 + (size_t)tid * 128);
            }
            const char* xp = xsl + (size_t)(j * Dd + dk) * 36864;
            if (j == 0)
                taps_one(acc0, xp, wb + (0 * 27 + dk * 9) * 2048);
            else if (j == 3)
                taps_one(acc1, xp, wb + (2 * 27 + dk * 9) * 2048);
            else
                taps_two(acc0, acc1, xp,
                         wb + (j * 27 + dk * 9) * 2048,
                         wb + ((j - 1) * 27 + dk * 9) * 2048);
        }
    }

    // ---- epilogue: two outputs, per-warp smem staging ----
    float* st = stg + wid * STAGE_F;
    const int sl = lane & 15;
    const int fh = lane >> 4;
    const size_t fstr = (size_t)OL * OD * OE * OE;

#pragma unroll 1
    for (int o = 0; o < 2; ++o) {
        const int l = l0 + o;
#pragma unroll 1
        for (int mt = 0; mt < 3; mt++) {
#pragma unroll
            for (int nt = 0; nt < 4; nt++) {
                const int col = nt * 8 + 2 * tig;
                const float* a = o ? acc1[mt][nt] : acc0[mt][nt];
                st[g * 33 + col]           = a[0];
                st[g * 33 + col + 1]       = a[1];
                st[(g + 8) * 33 + col]     = a[2];
                st[(g + 8) * 33 + col + 1] = a[3];
            }
            __syncwarp();
            const int s  = wid * 48 + mt * 16 + sl;     // 0..527, oh < 22 always
            const int oh = s / 24;
            const int ow = s - oh * 24;
            if (ow < OE) {
                const size_t base = ((((size_t)n * Ff) * OL + l) * OD + d) * (OE * OE)
                                    + (size_t)oh * OE + ow;
#pragma unroll
                for (int fp = 0; fp < 16; fp++) {
                    const int f = fp * 2 + fh;
                    out[base + (size_t)f * fstr] = st[sl * 33 + f] + sbias[f];
                }
            }
            __syncwarp();
        }
    }
}

// ---------------- launch ----------------
extern "C" void kernel_launch(void* const* d_in, const int* in_sizes, int n_in,
                              void* d_out, int out_size) {
    const float* x  = (const float*)d_in[0];
    const float* Wt = (const float*)d_in[1];
    const float* b  = (const float*)d_in[2];
    float* out = (float*)d_out;

    prep_all<<<Nn * Ll * Dd + 1, 256>>>(x, Wt);
    conv4d_mma<<<Nn * OL2 * OD, NT>>>(b, out);
}

// round 14
// speedup vs baseline: 2.0839x; 2.0839x over previous
#include <cuda_runtime.h>
#include <cstdint>

// ---------------- problem constants ----------------
#define Nn 8
#define Cc 16
#define Ll 32
#define Dd 24
#define HW24 576
#define Ff 32
#define OL 30
#define OD 22
#define OE 22

// ---------------- scratch (fragment-baked layouts) ----------------
// g_xt: [n][l][d][s=576][tig=4] float4; slot tig = channels (tig, tig+4, tig+8, tig+12)
__device__ float g_xt[(size_t)Nn * Ll * Dd * HW24 * Cc + 4096];
// g_w2: [pt=81][nt=4][n=8][tig=4] float4; pt = lk*27+dk*9+hk*3+wk; f = nt*8+n
__device__ float g_w2[9 * 9 * 4 * 8 * 16 + 512];

__device__ __forceinline__ uint32_t tf32_rna(float x) {
    uint32_t r;
    asm("cvt.rna.tf32.f32 %0, %1;" : "=r"(r) : "f"(x));
    return r;
}
__device__ __forceinline__ uint4 ldg128(const void* p) {
    return __ldg(reinterpret_cast<const uint4*>(p));
}
__device__ __forceinline__ void pf_l1(const void* p) {
    asm volatile("prefetch.global.L1 [%0];" :: "l"(p));
}
__device__ __forceinline__ void mma_tf32(float* d,
    uint32_t a0, uint32_t a1, uint32_t a2, uint32_t a3,
    uint32_t b0, uint32_t b1)
{
    asm volatile(
        "mma.sync.aligned.m16n8k8.row.col.f32.tf32.tf32.f32 "
        "{%0,%1,%2,%3}, {%4,%5,%6,%7}, {%8,%9}, {%0,%1,%2,%3};"
        : "+f"(d[0]), "+f"(d[1]), "+f"(d[2]), "+f"(d[3])
        : "r"(a0), "r"(a1), "r"(a2), "r"(a3), "r"(b0), "r"(b1));
}

// ---------------- prep ----------------
__global__ __launch_bounds__(256)
void prep_all(const float* __restrict__ x, const float* __restrict__ W) {
    int bid = blockIdx.x;
    if (bid < Nn * Ll * Dd) {
        __shared__ float sx[Cc][HW24 + 1];
        int D = bid % Dd;
        int L = (bid / Dd) % Ll;
        int n = bid / (Dd * Ll);
        for (int i4 = threadIdx.x; i4 < Cc * 144; i4 += 256) {
            int c = i4 / 144, r4 = i4 - c * 144;
            const float4 v = *reinterpret_cast<const float4*>(
                x + ((((size_t)(n * Cc + c) * Ll + L) * Dd + D) * HW24 + r4 * 4));
            sx[c][r4 * 4 + 0] = v.x; sx[c][r4 * 4 + 1] = v.y;
            sx[c][r4 * 4 + 2] = v.z; sx[c][r4 * 4 + 3] = v.w;
        }
        __syncthreads();
        float4* dst = reinterpret_cast<float4*>(g_xt + (size_t)bid * (HW24 * Cc));
        for (int i4 = threadIdx.x; i4 < HW24 * 4; i4 += 256) {
            int s = i4 >> 2, tig = i4 & 3;
            uint4 v;
            v.x = tf32_rna(sx[tig][s]);
            v.y = tf32_rna(sx[tig + 4][s]);
            v.z = tf32_rna(sx[tig + 8][s]);
            v.w = tf32_rna(sx[tig + 12][s]);
            dst[i4] = *reinterpret_cast<float4*>(&v);
        }
    } else {
        for (int i = threadIdx.x; i < 9 * 9 * 4 * 8 * 4; i += 256) {
            int tig = i & 3;
            int nrow = (i >> 2) & 7;
            int nt = (i >> 5) & 3;
            int pt = i >> 7;
            int f = nt * 8 + nrow;
            uint4 v;
            v.x = tf32_rna(W[((size_t)f * Cc + tig) * 81 + pt]);
            v.y = tf32_rna(W[((size_t)f * Cc + tig + 4) * 81 + pt]);
            v.z = tf32_rna(W[((size_t)f * Cc + tig + 8) * 81 + pt]);
            v.w = tf32_rna(W[((size_t)f * Cc + tig + 12) * 81 + pt]);
            reinterpret_cast<uint4*>(g_w2)[i] = v;
        }
    }
}

// ---------------- main: 11 warps x m48 x n16 (filter split), 2 CTAs/SM ----------------
#define STAGE_F (16 * 17)
#define NW 11
#define NT (NW * 32)

__global__ __launch_bounds__(NT, 2)
void conv4d_mma(const float* __restrict__ bias, float* __restrict__ out) {
    __shared__ float stg[NW * STAGE_F];
    __shared__ float sbias[16];

    const int tid  = threadIdx.x;
    const int wid  = tid >> 5;          // 0..10
    const int lane = tid & 31;
    const int g    = lane >> 2;
    const int tig  = lane & 3;

    int bid = blockIdx.x;
    const int fg = bid & 1;             // filter group: 0 -> f0..15, 1 -> f16..31
    int t = bid >> 1;
    const int d = t % OD;
    const int l = (t / OD) % OL;
    const int n = t / (OD * OL);

    if (tid < 16) sbias[tid] = 3.0f * bias[fg * 16 + tid];

    float acc[3][2][4];
#pragma unroll
    for (int mt = 0; mt < 3; mt++)
#pragma unroll
        for (int nt = 0; nt < 2; nt++)
#pragma unroll
            for (int k = 0; k < 4; k++) acc[mt][nt][k] = 0.f;

    const char* xblk = reinterpret_cast<const char*>(
        g_xt + ((size_t)((n * Ll + l) * Dd) + d) * (HW24 * Cc));
    const char* xsl = xblk + (size_t)(wid * 48 + g) * 64 + tig * 16;
    // filter half: nt block offset 512B, half fg at fg*1024
    const char* wb  = reinterpret_cast<const char*>(g_w2) + fg * 1024 + g * 64 + tig * 16;

#pragma unroll 1
    for (int p = 0; p < 9; ++p) {
        // prefetch next plane (A: 288 lines; B: our 72 lines)
        if (p + 1 < 9) {
            const size_t poff = (size_t)(((p + 1) / 3) * Dd + ((p + 1) % 3)) * (HW24 * 64);
            if (tid < 288) {
                pf_l1(xblk + poff + (size_t)tid * 128);
                if (tid < 72) {
                    const char* wnext = reinterpret_cast<const char*>(g_w2)
                        + (size_t)(p + 1) * 18432 + fg * 1024;
                    pf_l1(wnext + (size_t)(tid >> 3) * 2048 + (size_t)(tid & 7) * 128);
                }
            }
        }

        const char* xp = xsl + (size_t)((p / 3) * Dd + (p % 3)) * (HW24 * 64);
        const char* wp = wb + (size_t)p * 18432;

#pragma unroll
        for (int tap = 0; tap < 9; ++tap) {
            const int off = (tap / 3) * 24 + (tap % 3);
            uint4 bf[2];
#pragma unroll
            for (int nt = 0; nt < 2; nt++)
                bf[nt] = ldg128(wp + tap * 2048 + nt * 512);
#pragma unroll
            for (int mt = 0; mt < 3; mt++) {
                const uint4 a0 = ldg128(xp + (mt * 16 + off) * 64);
                const uint4 a1 = ldg128(xp + (mt * 16 + 8 + off) * 64);
#pragma unroll
                for (int nt = 0; nt < 2; nt++) {
                    mma_tf32(acc[mt][nt], a0.x, a1.x, a0.y, a1.y, bf[nt].x, bf[nt].y);
                    mma_tf32(acc[mt][nt], a0.z, a1.z, a0.w, a1.w, bf[nt].z, bf[nt].w);
                }
            }
        }
    }

    // ---- epilogue: per-warp smem staging, 16 filters ----
    float* st = stg + wid * STAGE_F;
    const int sl = lane & 15;
    const int fh = lane >> 4;
    const size_t fstr = (size_t)OL * OD * OE * OE;

#pragma unroll 1
    for (int mt = 0; mt < 3; mt++) {
#pragma unroll
        for (int nt = 0; nt < 2; nt++) {
            const int col = nt * 8 + 2 * tig;
            st[g * 17 + col]           = acc[mt][nt][0];
            st[g * 17 + col + 1]       = acc[mt][nt][1];
            st[(g + 8) * 17 + col]     = acc[mt][nt][2];
            st[(g + 8) * 17 + col + 1] = acc[mt][nt][3];
        }
        __syncwarp();
        const int s  = wid * 48 + mt * 16 + sl;     // 0..527, oh < 22 always
        const int oh = s / 24;
        const int ow = s - oh * 24;
        if (ow < OE) {
            const size_t base = ((((size_t)n * Ff + fg * 16) * OL + l) * OD + d) * (OE * OE)
                                + (size_t)oh * OE + ow;
#pragma unroll
            for (int fp = 0; fp < 8; fp++) {
                const int f = fp * 2 + fh;
                out[base + (size_t)f * fstr] = st[sl * 17 + f] + sbias[f];
            }
        }
        __syncwarp();
    }
}

// ---------------- launch ----------------
extern "C" void kernel_launch(void* const* d_in, const int* in_sizes, int n_in,
                              void* d_out, int out_size) {
    const float* x  = (const float*)d_in[0];
    const float* Wt = (const float*)d_in[1];
    const float* b  = (const float*)d_in[2];
    float* out = (float*)d_out;

    prep_all<<<Nn * Ll * Dd + 1, 256>>>(x, Wt);
    conv4d_mma<<<Nn * OL * OD * 2, NT>>>(b, out);
}

// round 15
// speedup vs baseline: 4.0126x; 1.9255x over previous
#include <cuda_runtime.h>
#include <cuda_fp16.h>
#include <cstdint>

// ---------------- problem constants ----------------
#define Nn 8
#define Cc 16
#define Ll 32
#define Dd 24
#define HW24 576
#define Ff 32
#define OL 30
#define OD 22
#define OE 22

// ---------------- scratch (fp16 fragment-baked layouts) ----------------
// g_xth: [n][l][d][s=576][16 halves, pair-permuted] (32B/row)
//   half index k in row: t=k/4, u=k%4; channel c = (u<2) ? 2t+u : 8+2t+(u-2)
__device__ __half g_xth[(size_t)Nn * Ll * Dd * HW24 * Cc + 8192];
// g_w2h: [pt=81][nt=4][j=8][16 halves same perm]; f = nt*8+j; pt = lk*27+dk*9+hk*3+wk
__device__ __half g_w2h[81 * 4 * 8 * 16 + 512];

__device__ __forceinline__ uint2 ldg64(const void* p) {
    return __ldg(reinterpret_cast<const uint2*>(p));
}
__device__ __forceinline__ void pf_l1(const void* p) {
    asm volatile("prefetch.global.L1 [%0];" :: "l"(p));
}
// fp16 MMA m16n8k16, fp32 accum
__device__ __forceinline__ void mma_f16(float* d,
    uint32_t a0, uint32_t a1, uint32_t a2, uint32_t a3,
    uint32_t b0, uint32_t b1)
{
    asm volatile(
        "mma.sync.aligned.m16n8k16.row.col.f32.f16.f16.f32 "
        "{%0,%1,%2,%3}, {%4,%5,%6,%7}, {%8,%9}, {%0,%1,%2,%3};"
        : "+f"(d[0]), "+f"(d[1]), "+f"(d[2]), "+f"(d[3])
        : "r"(a0), "r"(a1), "r"(a2), "r"(a3), "r"(b0), "r"(b1));
}

// ---------------- prep ----------------
__global__ __launch_bounds__(256)
void prep_all(const float* __restrict__ x, const float* __restrict__ W) {
    int bid = blockIdx.x;
    if (bid < Nn * Ll * Dd) {
        __shared__ float sx[Cc][HW24 + 1];
        int D = bid % Dd;
        int L = (bid / Dd) % Ll;
        int n = bid / (Dd * Ll);
        for (int i4 = threadIdx.x; i4 < Cc * 144; i4 += 256) {
            int c = i4 / 144, r4 = i4 - c * 144;
            const float4 v = *reinterpret_cast<const float4*>(
                x + ((((size_t)(n * Cc + c) * Ll + L) * Dd + D) * HW24 + r4 * 4));
            sx[c][r4 * 4 + 0] = v.x; sx[c][r4 * 4 + 1] = v.y;
            sx[c][r4 * 4 + 2] = v.z; sx[c][r4 * 4 + 3] = v.w;
        }
        __syncthreads();
        __half* dst = g_xth + (size_t)bid * (HW24 * Cc);
        for (int i = threadIdx.x; i < HW24 * Cc; i += 256) {
            int s = i >> 4, k = i & 15;
            int t = k >> 2, u = k & 3;
            int c = (u < 2) ? (2 * t + u) : (8 + 2 * t + (u - 2));
            dst[s * 16 + k] = __float2half_rn(sx[c][s]);
        }
    } else {
        for (int i = threadIdx.x; i < 81 * 4 * 8 * 16; i += 256) {
            int k = i & 15;
            int j = (i >> 4) & 7;
            int nt = (i >> 7) & 3;
            int pt = i >> 9;
            int t = k >> 2, u = k & 3;
            int c = (u < 2) ? (2 * t + u) : (8 + 2 * t + (u - 2));
            int f = nt * 8 + j;
            g_w2h[i] = __float2half_rn(W[((size_t)f * Cc + c) * 81 + pt]);
        }
    }
}

// ---------------- main: 11 warps x m48 x n32, fp16 m16n8k16 ----------------
#define STAGE_F (16 * 33)
#define NW 11
#define NT (NW * 32)

__global__ __launch_bounds__(NT, 1)
void conv4d_mma(const float* __restrict__ bias, float* __restrict__ out) {
    __shared__ float stg[NW * STAGE_F];
    __shared__ float sbias[Ff];

    const int tid  = threadIdx.x;
    const int wid  = tid >> 5;          // 0..10
    const int lane = tid & 31;
    const int g    = lane >> 2;
    const int tig  = lane & 3;

    int bid = blockIdx.x;
    const int d = bid % OD;
    const int l = (bid / OD) % OL;
    const int n = bid / (OD * OL);

    if (tid < Ff) sbias[tid] = 3.0f * bias[tid];

    float acc[3][4][4];
#pragma unroll
    for (int mt = 0; mt < 3; mt++)
#pragma unroll
        for (int nt = 0; nt < 4; nt++)
#pragma unroll
            for (int k = 0; k < 4; k++) acc[mt][nt][k] = 0.f;

    // A: row stride 32B, plane stride 576*32 = 18432B
    const char* xblk = reinterpret_cast<const char*>(
        g_xth + ((size_t)((n * Ll + l) * Dd) + d) * (HW24 * Cc));
    const char* xsl = xblk + (size_t)(wid * 48 + g) * 32 + tig * 8;
    // B: row(j) 32B, nt stride 256B, tap stride 1024B, plane stride 9216B
    const char* wb  = reinterpret_cast<const char*>(g_w2h) + g * 32 + tig * 8;

#pragma unroll 1
    for (int p = 0; p < 9; ++p) {
        // prefetch next plane (A: 144 lines, B: 72 lines)
        if (p + 1 < 9) {
            const size_t poff = (size_t)(((p + 1) / 3) * Dd + ((p + 1) % 3)) * 18432;
            if (tid < 144)
                pf_l1(xblk + poff + (size_t)tid * 128);
            else if (tid < 216)
                pf_l1(reinterpret_cast<const char*>(g_w2h) + (size_t)(p + 1) * 9216
                      + (size_t)(tid - 144) * 128);
        }

        const char* xp = xsl + (size_t)((p / 3) * Dd + (p % 3)) * 18432;
        const char* wp = wb + (size_t)p * 9216;

#pragma unroll
        for (int tap = 0; tap < 9; ++tap) {
            const int off = (tap / 3) * 24 + (tap % 3);
            uint2 bf[4];
#pragma unroll
            for (int nt = 0; nt < 4; nt++)
                bf[nt] = ldg64(wp + tap * 1024 + nt * 256);
#pragma unroll
            for (int mt = 0; mt < 3; mt++) {
                const uint2 alo = ldg64(xp + (mt * 16 + off) * 32);        // row g:   (a0,a2)
                const uint2 ahi = ldg64(xp + (mt * 16 + 8 + off) * 32);    // row g+8: (a1,a3)
#pragma unroll
                for (int nt = 0; nt < 4; nt++)
                    mma_f16(acc[mt][nt], alo.x, ahi.x, alo.y, ahi.y,
                            bf[nt].x, bf[nt].y);
            }
        }
    }

    // ---- epilogue: per-warp smem staging for coalesced stores ----
    float* st = stg + wid * STAGE_F;
    const int sl = lane & 15;
    const int fh = lane >> 4;

#pragma unroll 1
    for (int mt = 0; mt < 3; mt++) {
#pragma unroll
        for (int nt = 0; nt < 4; nt++) {
            const int col = nt * 8 + 2 * tig;
            st[g * 33 + col]           = acc[mt][nt][0];
            st[g * 33 + col + 1]       = acc[mt][nt][1];
            st[(g + 8) * 33 + col]     = acc[mt][nt][2];
            st[(g + 8) * 33 + col + 1] = acc[mt][nt][3];
        }
        __syncwarp();
        const int s  = wid * 48 + mt * 16 + sl;     // 0..527, oh always < 22
        const int oh = s / 24;
        const int ow = s - oh * 24;
        if (ow < OE) {
            const size_t base = ((((size_t)n * Ff) * OL + l) * OD + d) * (OE * OE)
                                + (size_t)oh * OE + ow;
            const size_t fstr = (size_t)OL * OD * OE * OE;
#pragma unroll
            for (int fp = 0; fp < 16; fp++) {
                const int f = fp * 2 + fh;
                out[base + (size_t)f * fstr] = st[sl * 33 + f] + sbias[f];
            }
        }
        __syncwarp();
    }
}

// ---------------- launch ----------------
extern "C" void kernel_launch(void* const* d_in, const int* in_sizes, int n_in,
                              void* d_out, int out_size) {
    const float* x  = (const float*)d_in[0];
    const float* Wt = (const float*)d_in[1];
    const float* b  = (const float*)d_in[2];
    float* out = (float*)d_out;

    prep_all<<<Nn * Ll * Dd + 1, 256>>>(x, Wt);
    conv4d_mma<<<Nn * OL * OD, NT>>>(b, out);
}

// round 16
// speedup vs baseline: 4.0267x; 1.0035x over previous
#include <cuda_runtime.h>
#include <cuda_fp16.h>
#include <cstdint>

// ---------------- problem constants ----------------
#define Nn 8
#define Cc 16
#define Ll 32
#define Dd 24
#define HW24 576
#define Ff 32
#define OL 30
#define OD 22
#define OE 22

// ---------------- scratch (fp16 fragment-baked layouts) ----------------
// g_xth: [n][l][d][s=576][16 halves, pair-permuted] (32B/row)
//   half index k in row: t=k/4, u=k%4; channel c = (u<2) ? 2t+u : 8+2t+(u-2)
__device__ __half g_xth[(size_t)Nn * Ll * Dd * HW24 * Cc + 8192];
// g_w2h: [pt=81][nt=4][j=8][16 halves same perm]; f = nt*8+j; pt = lk*27+dk*9+hk*3+wk
__device__ __half g_w2h[81 * 4 * 8 * 16 + 512];

__device__ __forceinline__ uint2 ldg64(const void* p) {
    return __ldg(reinterpret_cast<const uint2*>(p));
}
__device__ __forceinline__ void pf_l1(const void* p) {
    asm volatile("prefetch.global.L1 [%0];" :: "l"(p));
}
// fp16 MMA m16n8k16, fp32 accum
__device__ __forceinline__ void mma_f16(float* d,
    uint32_t a0, uint32_t a1, uint32_t a2, uint32_t a3,
    uint32_t b0, uint32_t b1)
{
    asm volatile(
        "mma.sync.aligned.m16n8k16.row.col.f32.f16.f16.f32 "
        "{%0,%1,%2,%3}, {%4,%5,%6,%7}, {%8,%9}, {%0,%1,%2,%3};"
        : "+f"(d[0]), "+f"(d[1]), "+f"(d[2]), "+f"(d[3])
        : "r"(a0), "r"(a1), "r"(a2), "r"(a3), "r"(b0), "r"(b1));
}

// ---------------- prep ----------------
__global__ __launch_bounds__(256)
void prep_all(const float* __restrict__ x, const float* __restrict__ W) {
    int bid = blockIdx.x;
    if (bid < Nn * Ll * Dd) {
        __shared__ float sx[Cc][HW24 + 1];
        int D = bid % Dd;
        int L = (bid / Dd) % Ll;
        int n = bid / (Dd * Ll);
        for (int i4 = threadIdx.x; i4 < Cc * 144; i4 += 256) {
            int c = i4 / 144, r4 = i4 - c * 144;
            const float4 v = *reinterpret_cast<const float4*>(
                x + ((((size_t)(n * Cc + c) * Ll + L) * Dd + D) * HW24 + r4 * 4));
            sx[c][r4 * 4 + 0] = v.x; sx[c][r4 * 4 + 1] = v.y;
            sx[c][r4 * 4 + 2] = v.z; sx[c][r4 * 4 + 3] = v.w;
        }
        __syncthreads();
        __half* dst = g_xth + (size_t)bid * (HW24 * Cc);
        for (int i = threadIdx.x; i < HW24 * Cc; i += 256) {
            int s = i >> 4, k = i & 15;
            int t = k >> 2, u = k & 3;
            int c = (u < 2) ? (2 * t + u) : (8 + 2 * t + (u - 2));
            dst[s * 16 + k] = __float2half_rn(sx[c][s]);
        }
    } else {
        for (int i = threadIdx.x; i < 81 * 4 * 8 * 16; i += 256) {
            int k = i & 15;
            int j = (i >> 4) & 7;
            int nt = (i >> 7) & 3;
            int pt = i >> 9;
            int t = k >> 2, u = k & 3;
            int c = (u < 2) ? (2 * t + u) : (8 + 2 * t + (u - 2));
            int f = nt * 8 + j;
            g_w2h[i] = __float2half_rn(W[((size_t)f * Cc + c) * 81 + pt]);
        }
    }
}

// ---------------- main: 17 warps x m32 x n32, fp16 m16n8k16 ----------------
#define STAGE_F (16 * 33)
#define NW 17
#define NT (NW * 32)

__global__ __launch_bounds__(NT, 1)
void conv4d_mma(const float* __restrict__ bias, float* __restrict__ out) {
    __shared__ float stg[NW * STAGE_F];
    __shared__ float sbias[Ff];

    const int tid  = threadIdx.x;
    const int wid  = tid >> 5;          // 0..16
    const int lane = tid & 31;
    const int g    = lane >> 2;
    const int tig  = lane & 3;

    int bid = blockIdx.x;
    const int d = bid % OD;
    const int l = (bid / OD) % OL;
    const int n = bid / (OD * OL);

    if (tid < Ff) sbias[tid] = 3.0f * bias[tid];

    float acc[2][4][4];
#pragma unroll
    for (int mt = 0; mt < 2; mt++)
#pragma unroll
        for (int nt = 0; nt < 4; nt++)
#pragma unroll
            for (int k = 0; k < 4; k++) acc[mt][nt][k] = 0.f;

    // A: row stride 32B, plane stride 576*32 = 18432B
    const char* xblk = reinterpret_cast<const char*>(
        g_xth + ((size_t)((n * Ll + l) * Dd) + d) * (HW24 * Cc));
    const char* xsl = xblk + (size_t)(wid * 32 + g) * 32 + tig * 8;
    // B: row(j) 32B, nt stride 256B, tap stride 1024B, plane stride 9216B
    const char* wb  = reinterpret_cast<const char*>(g_w2h) + g * 32 + tig * 8;

    const bool full = (wid < 16);       // warp 16: only mt=0 rows are valid output

#pragma unroll 1
    for (int p = 0; p < 9; ++p) {
        // prefetch next plane (A: 144 lines, B: 72 lines)
        if (p + 1 < 9) {
            const size_t poff = (size_t)(((p + 1) / 3) * Dd + ((p + 1) % 3)) * 18432;
            if (tid < 144)
                pf_l1(xblk + poff + (size_t)tid * 128);
            else if (tid < 216)
                pf_l1(reinterpret_cast<const char*>(g_w2h) + (size_t)(p + 1) * 9216
                      + (size_t)(tid - 144) * 128);
        }

        const char* xp = xsl + (size_t)((p / 3) * Dd + (p % 3)) * 18432;
        const char* wp = wb + (size_t)p * 9216;

#pragma unroll
        for (int tap = 0; tap < 9; ++tap) {
            const int off = (tap / 3) * 24 + (tap % 3);
            uint2 bf[4];
#pragma unroll
            for (int nt = 0; nt < 4; nt++)
                bf[nt] = ldg64(wp + tap * 1024 + nt * 256);

            {   // mt = 0
                const uint2 alo = ldg64(xp + off * 32);
                const uint2 ahi = ldg64(xp + (8 + off) * 32);
#pragma unroll
                for (int nt = 0; nt < 4; nt++)
                    mma_f16(acc[0][nt], alo.x, ahi.x, alo.y, ahi.y,
                            bf[nt].x, bf[nt].y);
            }
            if (full) {   // mt = 1 (uniform per-warp branch)
                const uint2 alo = ldg64(xp + (16 + off) * 32);
                const uint2 ahi = ldg64(xp + (24 + off) * 32);
#pragma unroll
                for (int nt = 0; nt < 4; nt++)
                    mma_f16(acc[1][nt], alo.x, ahi.x, alo.y, ahi.y,
                            bf[nt].x, bf[nt].y);
            }
        }
    }

    // ---- epilogue: per-warp smem staging for coalesced stores ----
    float* st = stg + wid * STAGE_F;
    const int sl = lane & 15;
    const int fh = lane >> 4;
    const int mtmax = full ? 2 : 1;

#pragma unroll 1
    for (int mt = 0; mt < mtmax; mt++) {
#pragma unroll
        for (int nt = 0; nt < 4; nt++) {
            const int col = nt * 8 + 2 * tig;
            st[g * 33 + col]           = acc[mt][nt][0];
            st[g * 33 + col + 1]       = acc[mt][nt][1];
            st[(g + 8) * 33 + col]     = acc[mt][nt][2];
            st[(g + 8) * 33 + col + 1] = acc[mt][nt][3];
        }
        __syncwarp();
        const int s  = wid * 32 + mt * 16 + sl;
        const int oh = s / 24;
        const int ow = s - oh * 24;
        if (oh < OE && ow < OE) {
            const size_t base = ((((size_t)n * Ff) * OL + l) * OD + d) * (OE * OE)
                                + (size_t)oh * OE + ow;
            const size_t fstr = (size_t)OL * OD * OE * OE;
#pragma unroll
            for (int fp = 0; fp < 16; fp++) {
                const int f = fp * 2 + fh;
                out[base + (size_t)f * fstr] = st[sl * 33 + f] + sbias[f];
            }
        }
        __syncwarp();
    }
}

// ---------------- launch ----------------
extern "C" void kernel_launch(void* const* d_in, const int* in_sizes, int n_in,
                              void* d_out, int out_size) {
    const float* x  = (const float*)d_in[0];
    const float* Wt = (const float*)d_in[1];
    const float* b  = (const float*)d_in[2];
    float* out = (float*)d_out;

    prep_all<<<Nn * Ll * Dd + 1, 256>>>(x, Wt);
    conv4d_mma<<<Nn * OL * OD, NT>>>(b, out);
}